// round 12
// baseline (speedup 1.0000x reference)
#include <cuda_runtime.h>
#include <cuda_fp16.h>
#include <cstdint>
#include <math.h>

// Problem constants
#define Bv   4
#define Nv   4096
#define Cv   1024
#define Hv   16
#define Dv   64
#define BSv  64
#define NBv  64
#define Mv   (Bv * Nv)   // 16384 rows

typedef __half h16;

// ---------------------------------------------------------------------------
// Scratch (device globals; no runtime allocation allowed)
// ---------------------------------------------------------------------------
__device__ h16 g_Xh[(size_t)Mv * Cv];
__device__ h16 g_Qh[(size_t)Mv * Cv];
__device__ h16 g_Kh[(size_t)Mv * Cv];
__device__ h16 g_Kl[(size_t)Mv * Cv];
__device__ h16 g_Vh[(size_t)Mv * Cv];
__device__ h16 g_Vl[(size_t)Mv * Cv];
__device__ h16 g_Oh[(size_t)Mv * Cv];
__device__ h16 g_Wh[4 * (size_t)Cv * Cv];
__device__ h16 g_Wl[4 * (size_t)Cv * Cv];

__device__ __forceinline__ uint32_t smem_u32(const void* p) {
    return (uint32_t)__cvta_generic_to_shared(p);
}

__device__ __forceinline__ void cp16(uint32_t saddr, const void* gaddr) {
    asm volatile("cp.async.cg.shared.global [%0], [%1], 16;"
                 :: "r"(saddr), "l"(gaddr));
}

__device__ __forceinline__ void ldx4(uint32_t* r, uint32_t addr) {
    asm volatile("ldmatrix.sync.aligned.m8n8.x4.shared.b16 {%0,%1,%2,%3}, [%4];"
                 : "=r"(r[0]), "=r"(r[1]), "=r"(r[2]), "=r"(r[3]) : "r"(addr));
}

__device__ __forceinline__ void mma16816(float* d, const uint32_t* a,
                                         uint32_t b0, uint32_t b1) {
    asm volatile("mma.sync.aligned.m16n8k16.row.col.f32.f16.f16.f32 "
                 "{%0,%1,%2,%3}, {%4,%5,%6,%7}, {%8,%9}, {%0,%1,%2,%3};"
                 : "+f"(d[0]), "+f"(d[1]), "+f"(d[2]), "+f"(d[3])
                 : "r"(a[0]), "r"(a[1]), "r"(a[2]), "r"(a[3]), "r"(b0), "r"(b1));
}

__device__ __forceinline__ uint32_t pack2h(float a, float b) {
    __half2 t(__float2half_rn(a), __float2half_rn(b));
    return *(uint32_t*)&t;
}

// ---------------------------------------------------------------------------
// Splits: fp32 -> fp16 hi (+ optional fp16 lo = rn(x - float(hi)))
// ---------------------------------------------------------------------------
__global__ __launch_bounds__(256) void split_hi(
    const float* __restrict__ src, h16* __restrict__ hi, int n4)
{
    int i = blockIdx.x * blockDim.x + threadIdx.x;
    if (i >= n4) return;
    float4 v = *(const float4*)(src + (size_t)i * 4);
    uint2 hp;
    hp.x = pack2h(v.x, v.y); hp.y = pack2h(v.z, v.w);
    *(uint2*)(hi + (size_t)i * 4) = hp;
}

__global__ __launch_bounds__(256) void split_hilo(
    const float* __restrict__ src, h16* __restrict__ hi,
    h16* __restrict__ lo, int n4)
{
    int i = blockIdx.x * blockDim.x + threadIdx.x;
    if (i >= n4) return;
    float4 v = *(const float4*)(src + (size_t)i * 4);
    h16 h0 = __float2half_rn(v.x), h1 = __float2half_rn(v.y);
    h16 h2 = __float2half_rn(v.z), h3 = __float2half_rn(v.w);
    uint2 hp, lp;
    __half2 t01(h0, h1), t23(h2, h3);
    hp.x = *(uint32_t*)&t01; hp.y = *(uint32_t*)&t23;
    lp.x = pack2h(v.x - __half2float(h0), v.y - __half2float(h1));
    lp.y = pack2h(v.z - __half2float(h2), v.w - __half2float(h3));
    *(uint2*)(hi + (size_t)i * 4) = hp;
    *(uint2*)(lo + (size_t)i * 4) = lp;
}

// ---------------------------------------------------------------------------
// HMMA GEMM, 2-product fp16: Y ~= Ahi*(Bhi + Blo). CTA 128x128, 8 warps 64x32.
// 2-stage cp.async ring (110 KB -> 2 CTAs/SM). B-frags via paired ldmatrix.x4.
// MODE 0: fp32 out (+bias b0p).
// MODE 1: merged QKV — grid.x=24; sel=blockIdx.x>>3 -> (Qh/-, Kh/Kl, Vh/Vl).
// ---------------------------------------------------------------------------
#define CHUNKS   16
#define RSB      144
#define TILE_B   (128 * RSB)               // 18432
#define STAGE_B  (3 * TILE_B)              // 55296
#define GEMM_SMEM (2 * STAGE_B)            // 110592

template<int MODE>
__global__ __launch_bounds__(256, 1) void gemm_mma(
    const h16* __restrict__ Ah,
    const h16* __restrict__ Bh, const h16* __restrict__ Bl,
    const float* __restrict__ b0p, const float* __restrict__ b1p,
    const float* __restrict__ b2p,
    float* __restrict__ Y,
    h16* __restrict__ O0h, h16* __restrict__ O0l,
    h16* __restrict__ O1h, h16* __restrict__ O1l,
    h16* __restrict__ O2h, h16* __restrict__ O2l)
{
    extern __shared__ __align__(16) char smem[];

    const int tid   = threadIdx.x;
    const int lane  = tid & 31;
    const int wid   = tid >> 5;
    const int warp_m = wid >> 2;     // 0..1 : 64 rows
    const int warp_n = wid & 3;      // 0..3 : 32 cols
    const int n0 = blockIdx.x * 128;       // col into (possibly concat) B
    const int m0 = blockIdx.y * 128;

    const h16* srcs[3] = {
        Ah + (size_t)m0 * Cv, Bh + (size_t)n0 * Cv, Bl + (size_t)n0 * Cv };

    const uint32_t sb = smem_u32(smem);

    float acc[4][4][4];
#pragma unroll
    for (int mi = 0; mi < 4; mi++)
#pragma unroll
        for (int ni = 0; ni < 4; ni++)
#pragma unroll
            for (int f = 0; f < 4; f++) acc[mi][ni][f] = 0.f;

    auto load_stage = [&](int c, int s) {
        const int k0 = c * 64;
        const uint32_t base = sb + s * STAGE_B;
#pragma unroll
        for (int j = 0; j < 12; j++) {
            int chunk = tid + j * 256;       // 0..3071
            int t   = chunk >> 10;           // 0..2 : Ah, Bh, Bl
            int i   = chunk & 1023;
            int row = i >> 3;
            int c16 = i & 7;
            cp16(base + t * TILE_B + row * RSB + c16 * 16,
                 srcs[t] + (size_t)row * Cv + k0 + c16 * 8);
        }
        asm volatile("cp.async.commit_group;" ::: "memory");
    };

    load_stage(0, 0);

    const int ra = lane & 15;
    const int ca = (lane >> 4) * 8;

    for (int c = 0; c < CHUNKS; c++) {
        const int s = c & 1;
        if (c + 1 < CHUNKS) {
            load_stage(c + 1, (c + 1) & 1);
            asm volatile("cp.async.wait_group 1;" ::: "memory");
        } else {
            asm volatile("cp.async.wait_group 0;" ::: "memory");
        }
        __syncthreads();

        const uint32_t base = sb + s * STAGE_B;
        const uint32_t aH = base + 0 * TILE_B;
        const uint32_t bH = base + 1 * TILE_B;
        const uint32_t bL = base + 2 * TILE_B;

#pragma unroll
        for (int ks = 0; ks < 4; ks++) {
            const int k16 = ks * 16;
            uint32_t ah[4][4], bh[2][4], bl[2][4];
#pragma unroll
            for (int mi = 0; mi < 4; mi++) {
                uint32_t off = (warp_m * 64 + mi * 16 + ra) * RSB + (k16 + ca) * 2;
                ldx4(ah[mi], aH + off);
            }
#pragma unroll
            for (int pb = 0; pb < 2; pb++) {
                uint32_t boff = (warp_n * 32 + pb * 16 + ra) * RSB + (k16 + ca) * 2;
                ldx4(bh[pb], bH + boff);
                ldx4(bl[pb], bL + boff);
            }
#pragma unroll
            for (int mi = 0; mi < 4; mi++)
#pragma unroll
                for (int pb = 0; pb < 2; pb++)
#pragma unroll
                    for (int hf = 0; hf < 2; hf++) {
                        int ni = pb * 2 + hf;
                        mma16816(acc[mi][ni], ah[mi], bh[pb][hf], bh[pb][hf + 2]);
                        mma16816(acc[mi][ni], ah[mi], bl[pb][hf], bl[pb][hf + 2]);
                    }
        }
        __syncthreads();
    }

    const int er = lane >> 2;
    const int ec = (lane & 3) * 2;

    if (MODE == 0) {
#pragma unroll
        for (int mi = 0; mi < 4; mi++)
#pragma unroll
            for (int ni = 0; ni < 4; ni++) {
                int m = m0 + warp_m * 64 + mi * 16 + er;
                int n = n0 + warp_n * 32 + ni * 8 + ec;
                float bb0 = b0p[n], bb1 = b0p[n + 1];
                float* d = acc[mi][ni];
                *(float2*)(Y + (size_t)m * Cv + n) = make_float2(d[0] + bb0, d[1] + bb1);
                *(float2*)(Y + (size_t)(m + 8) * Cv + n) = make_float2(d[2] + bb0, d[3] + bb1);
            }
    } else {
        const int sel = blockIdx.x >> 3;
        const int nl0 = (blockIdx.x & 7) * 128;
        const float* bias = (sel == 0) ? b0p : (sel == 1) ? b1p : b2p;
        h16* Yh = (sel == 0) ? O0h : (sel == 1) ? O1h : O2h;
        h16* Yl = (sel == 0) ? O0l : (sel == 1) ? O1l : O2l;
#pragma unroll
        for (int mi = 0; mi < 4; mi++)
#pragma unroll
            for (int ni = 0; ni < 4; ni++) {
                int m = m0 + warp_m * 64 + mi * 16 + er;
                int n = nl0 + warp_n * 32 + ni * 8 + ec;
                float bb0 = bias[n], bb1 = bias[n + 1];
                float* d = acc[mi][ni];
#pragma unroll
                for (int rr = 0; rr < 2; rr++) {
                    int mm = m + rr * 8;
                    float v0 = d[rr * 2 + 0] + bb0;
                    float v1 = d[rr * 2 + 1] + bb1;
                    h16 h0 = __float2half_rn(v0);
                    h16 h1 = __float2half_rn(v1);
                    __half2 hp(h0, h1);
                    *(uint32_t*)(Yh + (size_t)mm * Cv + n) = *(uint32_t*)&hp;
                    if (Yl)
                        *(uint32_t*)(Yl + (size_t)mm * Cv + n) =
                            pack2h(v0 - __half2float(h0), v1 - __half2float(h1));
                }
            }
    }
}

// ---------------------------------------------------------------------------
// Tensor-core block-sparse attention, 2-product fp16 (unchanged, validated).
// ---------------------------------------------------------------------------
#define ARS 144
#define PRS 272
#define OFF_QH   0
#define OFF_KH   9216
#define OFF_KL   27648
#define OFF_VTH  46080
#define OFF_VTL  63488
#define OFF_PH   80896
#define OFF_RMAX 98304
#define OFF_RSUM 98816
#define ATTN_SMEM 99328

__global__ __launch_bounds__(256, 1) void attn_tc(
    const h16* __restrict__ Qh,
    const h16* __restrict__ Kh, const h16* __restrict__ Kl,
    const h16* __restrict__ Vh, const h16* __restrict__ Vl,
    h16* __restrict__ Oh)
{
    extern __shared__ __align__(16) char sm[];
    const int tid  = threadIdx.x;
    const int lane = tid & 31;
    const int wid  = tid >> 5;
    const int warp_m = wid >> 1;
    const int warp_n = wid & 1;
    const int nb = blockIdx.x, h = blockIdx.y, b = blockIdx.z;
    const int qrow0 = b * Nv + nb * BSv;
    const int col0  = h * Dv;
    const int kb0 = (nb > 0) ? nb - 1 : 0;

    const uint32_t sb = smem_u32(sm);

#pragma unroll
    for (int it = 0; it < 2; it++) {
        int i = it * 256 + tid;
        int r = i >> 3, c = i & 7;
        cp16(sb + OFF_QH + r * ARS + c * 16,
             Qh + (size_t)(qrow0 + r) * Cv + col0 + c * 8);
    }
#pragma unroll
    for (int it = 0; it < 8; it++) {
        int lin = it * 256 + tid;
        int t = lin >> 10, i = lin & 1023;
        int r = i >> 3, c = i & 7;
        int krow = b * Nv + (r < 64 ? kb0 * 64 + r : nb * 64 + (r - 64));
        const h16* src = (t ? Kl : Kh) + (size_t)krow * Cv + col0 + c * 8;
        cp16(sb + (t ? OFF_KL : OFF_KH) + r * ARS + c * 16, src);
    }
    asm volatile("cp.async.commit_group;" ::: "memory");

#pragma unroll
    for (int t = 0; t < 2; t++) {
        const h16* Vsrc = t ? Vl : Vh;
        char* vt = sm + (t ? OFF_VTL : OFF_VTH);
#pragma unroll
        for (int it = 0; it < 16; it++) {
            int lin = it * 256 + tid;
            int key = lin >> 5, dp = lin & 31;
            int krow = b * Nv + (key < 64 ? kb0 * 64 + key : nb * 64 + (key - 64));
            uint32_t v = *(const uint32_t*)(Vsrc + (size_t)krow * Cv + col0 + dp * 2);
            *(uint16_t*)(vt + (2 * dp + 0) * PRS + key * 2) = (uint16_t)(v & 0xffff);
            *(uint16_t*)(vt + (2 * dp + 1) * PRS + key * 2) = (uint16_t)(v >> 16);
        }
    }
    asm volatile("cp.async.wait_group 0;" ::: "memory");
    __syncthreads();

    const int ra = lane & 15;
    const int ca = (lane >> 4) * 8;
    float acc[8][4];
#pragma unroll
    for (int ni = 0; ni < 8; ni++)
#pragma unroll
        for (int f = 0; f < 4; f++) acc[ni][f] = 0.f;

#pragma unroll
    for (int ks = 0; ks < 4; ks++) {
        uint32_t ah[4];
        uint32_t aoff = (warp_m * 16 + ra) * ARS + (ks * 16 + ca) * 2;
        ldx4(ah, sb + OFF_QH + aoff);
        uint32_t bh[4][4], bl[4][4];
#pragma unroll
        for (int pb = 0; pb < 4; pb++) {
            uint32_t boff = (warp_n * 64 + pb * 16 + ra) * ARS + (ks * 16 + ca) * 2;
            ldx4(bh[pb], sb + OFF_KH + boff);
            ldx4(bl[pb], sb + OFF_KL + boff);
        }
#pragma unroll
        for (int pb = 0; pb < 4; pb++)
#pragma unroll
            for (int hf = 0; hf < 2; hf++) {
                int ni = pb * 2 + hf;
                mma16816(acc[ni], ah, bh[pb][hf], bh[pb][hf + 2]);
                mma16816(acc[ni], ah, bl[pb][hf], bl[pb][hf + 2]);
            }
    }

    const int er = lane >> 2;
    const int ec = (lane & 3) * 2;
    const int iq = warp_m * 16 + er;
    const float scale = 0.125f;

#pragma unroll
    for (int ni = 0; ni < 8; ni++)
#pragma unroll
        for (int f = 0; f < 4; f++) {
            int i = iq + ((f >= 2) ? 8 : 0);
            int j = warp_n * 64 + ni * 8 + ec + (f & 1);
            bool valid = (64 + i >= j) && (nb > 0 || j >= 64);
            acc[ni][f] = valid ? acc[ni][f] * scale : -1e30f;
        }

    float m0 = -1e30f, m1 = -1e30f;
#pragma unroll
    for (int ni = 0; ni < 8; ni++) {
        m0 = fmaxf(m0, fmaxf(acc[ni][0], acc[ni][1]));
        m1 = fmaxf(m1, fmaxf(acc[ni][2], acc[ni][3]));
    }
    m0 = fmaxf(m0, __shfl_xor_sync(0xffffffffu, m0, 1));
    m0 = fmaxf(m0, __shfl_xor_sync(0xffffffffu, m0, 2));
    m1 = fmaxf(m1, __shfl_xor_sync(0xffffffffu, m1, 1));
    m1 = fmaxf(m1, __shfl_xor_sync(0xffffffffu, m1, 2));
    float* rmax = (float*)(sm + OFF_RMAX);
    if ((lane & 3) == 0) {
        rmax[iq * 2 + warp_n] = m0;
        rmax[(iq + 8) * 2 + warp_n] = m1;
    }
    __syncthreads();
    float g0 = fmaxf(rmax[iq * 2], rmax[iq * 2 + 1]);
    float g1 = fmaxf(rmax[(iq + 8) * 2], rmax[(iq + 8) * 2 + 1]);

    float s0 = 0.f, s1 = 0.f;
#pragma unroll
    for (int ni = 0; ni < 8; ni++) {
        acc[ni][0] = __expf(acc[ni][0] - g0);
        acc[ni][1] = __expf(acc[ni][1] - g0);
        acc[ni][2] = __expf(acc[ni][2] - g1);
        acc[ni][3] = __expf(acc[ni][3] - g1);
        s0 += acc[ni][0] + acc[ni][1];
        s1 += acc[ni][2] + acc[ni][3];
    }
    s0 += __shfl_xor_sync(0xffffffffu, s0, 1);
    s0 += __shfl_xor_sync(0xffffffffu, s0, 2);
    s1 += __shfl_xor_sync(0xffffffffu, s1, 1);
    s1 += __shfl_xor_sync(0xffffffffu, s1, 2);
    float* rsum = (float*)(sm + OFF_RSUM);
    if ((lane & 3) == 0) {
        rsum[iq * 2 + warp_n] = s0;
        rsum[(iq + 8) * 2 + warp_n] = s1;
    }
    __syncthreads();
    float inv0 = 1.f / (rsum[iq * 2] + rsum[iq * 2 + 1]);
    float inv1 = 1.f / (rsum[(iq + 8) * 2] + rsum[(iq + 8) * 2 + 1]);

#pragma unroll
    for (int ni = 0; ni < 8; ni++) {
        int j = warp_n * 64 + ni * 8 + ec;
        *(uint32_t*)(sm + OFF_PH + iq * PRS + j * 2) =
            pack2h(acc[ni][0] * inv0, acc[ni][1] * inv0);
        *(uint32_t*)(sm + OFF_PH + (iq + 8) * PRS + j * 2) =
            pack2h(acc[ni][2] * inv1, acc[ni][3] * inv1);
    }
    __syncthreads();

    float oacc[4][4];
#pragma unroll
    for (int ni = 0; ni < 4; ni++)
#pragma unroll
        for (int f = 0; f < 4; f++) oacc[ni][f] = 0.f;

#pragma unroll
    for (int ks = 0; ks < 8; ks++) {
        uint32_t ph[4];
        uint32_t aoff = (warp_m * 16 + ra) * PRS + (ks * 16 + ca) * 2;
        ldx4(ph, sb + OFF_PH + aoff);
        uint32_t vh[2][4], vl[2][4];
#pragma unroll
        for (int pb = 0; pb < 2; pb++) {
            uint32_t boff = (warp_n * 32 + pb * 16 + ra) * PRS + (ks * 16 + ca) * 2;
            ldx4(vh[pb], sb + OFF_VTH + boff);
            ldx4(vl[pb], sb + OFF_VTL + boff);
        }
#pragma unroll
        for (int pb = 0; pb < 2; pb++)
#pragma unroll
            for (int hf = 0; hf < 2; hf++) {
                int ni = pb * 2 + hf;
                mma16816(oacc[ni], ph, vh[pb][hf], vh[pb][hf + 2]);
                mma16816(oacc[ni], ph, vl[pb][hf], vl[pb][hf + 2]);
            }
    }

#pragma unroll
    for (int ni = 0; ni < 4; ni++) {
        int colg = col0 + warp_n * 32 + ni * 8 + ec;
        float* d = oacc[ni];
#pragma unroll
        for (int rr = 0; rr < 2; rr++) {
            int row = qrow0 + warp_m * 16 + er + rr * 8;
            *(uint32_t*)(Oh + (size_t)row * Cv + colg) =
                pack2h(d[rr * 2 + 0], d[rr * 2 + 1]);
        }
    }
}

// ---------------------------------------------------------------------------
extern "C" void kernel_launch(void* const* d_in, const int* in_sizes, int n_in,
                              void* d_out, int out_size)
{
    const float* x  = (const float*)d_in[0];
    const float* Wq = (const float*)d_in[1];
    const float* bq = (const float*)d_in[2];
    const float* Wk = (const float*)d_in[3];
    const float* bk = (const float*)d_in[4];
    const float* Wv = (const float*)d_in[5];
    const float* bv = (const float*)d_in[6];
    const float* Wo = (const float*)d_in[7];
    const float* bo = (const float*)d_in[8];
    float* out = (float*)d_out;

    void* p;
    h16 *Xh, *Qh, *Kh, *Kl, *Vh, *Vl, *Oh, *Wh, *Wl;
    cudaGetSymbolAddress(&p, g_Xh); Xh = (h16*)p;
    cudaGetSymbolAddress(&p, g_Qh); Qh = (h16*)p;
    cudaGetSymbolAddress(&p, g_Kh); Kh = (h16*)p;
    cudaGetSymbolAddress(&p, g_Kl); Kl = (h16*)p;
    cudaGetSymbolAddress(&p, g_Vh); Vh = (h16*)p;
    cudaGetSymbolAddress(&p, g_Vl); Vl = (h16*)p;
    cudaGetSymbolAddress(&p, g_Oh); Oh = (h16*)p;
    cudaGetSymbolAddress(&p, g_Wh); Wh = (h16*)p;
    cudaGetSymbolAddress(&p, g_Wl); Wl = (h16*)p;

    cudaFuncSetAttribute(gemm_mma<0>, cudaFuncAttributeMaxDynamicSharedMemorySize, GEMM_SMEM);
    cudaFuncSetAttribute(gemm_mma<1>, cudaFuncAttributeMaxDynamicSharedMemorySize, GEMM_SMEM);
    cudaFuncSetAttribute(attn_tc, cudaFuncAttributeMaxDynamicSharedMemorySize, ATTN_SMEM);

    const size_t WSZ = (size_t)Cv * Cv;
    const int xn4 = Mv * Cv / 4;
    const int wn4 = (int)(WSZ / 4);

    split_hi<<<xn4 / 256, 256>>>(x, Xh, xn4);
    split_hilo<<<wn4 / 256, 256>>>(Wq, Wh + 0 * WSZ, Wl + 0 * WSZ, wn4);
    split_hilo<<<wn4 / 256, 256>>>(Wk, Wh + 1 * WSZ, Wl + 1 * WSZ, wn4);
    split_hilo<<<wn4 / 256, 256>>>(Wv, Wh + 2 * WSZ, Wl + 2 * WSZ, wn4);
    split_hilo<<<wn4 / 256, 256>>>(Wo, Wh + 3 * WSZ, Wl + 3 * WSZ, wn4);

    // merged QKV projection; Q needs hi only (attention never reads Ql)
    dim3 gq(24, Mv / 128);   // (24, 128)
    gemm_mma<1><<<gq, 256, GEMM_SMEM>>>(Xh, Wh, Wl, bq, bk, bv,
                                        nullptr, Qh, nullptr, Kh, Kl, Vh, Vl);

    // tensor-core attention -> Oh (fp16 hi only)
    dim3 ga(NBv, Hv, Bv);
    attn_tc<<<ga, 256, ATTN_SMEM>>>(Qh, Kh, Kl, Vh, Vl, Oh);

    // output projection (fp32 out)
    dim3 gg(Cv / 128, Mv / 128);   // (8, 128)
    gemm_mma<0><<<gg, 256, GEMM_SMEM>>>(Oh, Wh + 3 * WSZ, Wl + 3 * WSZ,
                                        bo, nullptr, nullptr, out,
                                        nullptr, nullptr, nullptr, nullptr,
                                        nullptr, nullptr);
}

// round 14
// speedup vs baseline: 1.7392x; 1.7392x over previous
#include <cuda_runtime.h>
#include <cuda_fp16.h>
#include <cstdint>
#include <math.h>

// Problem constants
#define Bv   4
#define Nv   4096
#define Cv   1024
#define Hv   16
#define Dv   64
#define BSv  64
#define NBv  64
#define Mv   (Bv * Nv)   // 16384 rows

typedef __half h16;

// ---------------------------------------------------------------------------
// Scratch (device globals; no runtime allocation allowed)
// ---------------------------------------------------------------------------
__device__ h16 g_Xh[(size_t)Mv * Cv];
__device__ h16 g_Qh[(size_t)Mv * Cv];
__device__ h16 g_Kh[(size_t)Mv * Cv];
__device__ h16 g_Kl[(size_t)Mv * Cv];
__device__ h16 g_Vh[(size_t)Mv * Cv];
__device__ h16 g_Vl[(size_t)Mv * Cv];
__device__ h16 g_Oh[(size_t)Mv * Cv];
__device__ h16 g_Wh[4 * (size_t)Cv * Cv];

__device__ __forceinline__ uint32_t smem_u32(const void* p) {
    return (uint32_t)__cvta_generic_to_shared(p);
}

__device__ __forceinline__ void cp16(uint32_t saddr, const void* gaddr) {
    asm volatile("cp.async.cg.shared.global [%0], [%1], 16;"
                 :: "r"(saddr), "l"(gaddr));
}

__device__ __forceinline__ void ldx4(uint32_t* r, uint32_t addr) {
    asm volatile("ldmatrix.sync.aligned.m8n8.x4.shared.b16 {%0,%1,%2,%3}, [%4];"
                 : "=r"(r[0]), "=r"(r[1]), "=r"(r[2]), "=r"(r[3]) : "r"(addr));
}

__device__ __forceinline__ void mma16816(float* d, const uint32_t* a,
                                         uint32_t b0, uint32_t b1) {
    asm volatile("mma.sync.aligned.m16n8k16.row.col.f32.f16.f16.f32 "
                 "{%0,%1,%2,%3}, {%4,%5,%6,%7}, {%8,%9}, {%0,%1,%2,%3};"
                 : "+f"(d[0]), "+f"(d[1]), "+f"(d[2]), "+f"(d[3])
                 : "r"(a[0]), "r"(a[1]), "r"(a[2]), "r"(a[3]), "r"(b0), "r"(b1));
}

__device__ __forceinline__ uint32_t pack2h(float a, float b) {
    __half2 t(__float2half_rn(a), __float2half_rn(b));
    return *(uint32_t*)&t;
}

// ---------------------------------------------------------------------------
// Split: fp32 -> fp16 (round-to-nearest)
// ---------------------------------------------------------------------------
__global__ __launch_bounds__(256) void split_hi(
    const float* __restrict__ src, h16* __restrict__ hi, int n4)
{
    int i = blockIdx.x * blockDim.x + threadIdx.x;
    if (i >= n4) return;
    float4 v = *(const float4*)(src + (size_t)i * 4);
    uint2 hp;
    hp.x = pack2h(v.x, v.y); hp.y = pack2h(v.z, v.w);
    *(uint2*)(hi + (size_t)i * 4) = hp;
}

// ---------------------------------------------------------------------------
// HMMA GEMM, single-product fp16 (fp32 accum). CTA 128x128, 8 warps 64x32.
// 2-stage cp.async ring (73.7 KB -> >=2 CTAs/SM).
// MODE 0: fp32 out (+bias b0p).
// MODE 1: merged QKV — grid.x=24; sel=blockIdx.x>>3 -> (Qh/-, Kh/Kl, Vh/Vl);
//         K and V epilogues also emit fp16 lo residuals for the attention.
// ---------------------------------------------------------------------------
#define CHUNKS   16
#define RSB      144
#define TILE_B   (128 * RSB)               // 18432
#define STAGE_B  (2 * TILE_B)              // 36864
#define GEMM_SMEM (2 * STAGE_B)            // 73728

template<int MODE>
__global__ __launch_bounds__(256, 2) void gemm_mma(
    const h16* __restrict__ Ah, const h16* __restrict__ Bh,
    const float* __restrict__ b0p, const float* __restrict__ b1p,
    const float* __restrict__ b2p,
    float* __restrict__ Y,
    h16* __restrict__ O0h, h16* __restrict__ O0l,
    h16* __restrict__ O1h, h16* __restrict__ O1l,
    h16* __restrict__ O2h, h16* __restrict__ O2l)
{
    extern __shared__ __align__(16) char smem[];

    const int tid   = threadIdx.x;
    const int lane  = tid & 31;
    const int wid   = tid >> 5;
    const int warp_m = wid >> 2;     // 0..1 : 64 rows
    const int warp_n = wid & 3;      // 0..3 : 32 cols
    const int n0 = blockIdx.x * 128;       // col into (possibly concat) B
    const int m0 = blockIdx.y * 128;

    const h16* srcA = Ah + (size_t)m0 * Cv;
    const h16* srcB = Bh + (size_t)n0 * Cv;

    const uint32_t sb = smem_u32(smem);

    float acc[4][4][4];
#pragma unroll
    for (int mi = 0; mi < 4; mi++)
#pragma unroll
        for (int ni = 0; ni < 4; ni++)
#pragma unroll
            for (int f = 0; f < 4; f++) acc[mi][ni][f] = 0.f;

    auto load_stage = [&](int c, int s) {
        const int k0 = c * 64;
        const uint32_t base = sb + s * STAGE_B;
#pragma unroll
        for (int j = 0; j < 8; j++) {
            int chunk = tid + j * 256;       // 0..2047
            int t   = chunk >> 10;           // 0=A, 1=B
            int i   = chunk & 1023;
            int row = i >> 3;
            int c16 = i & 7;
            const h16* src = t ? srcB : srcA;
            cp16(base + t * TILE_B + row * RSB + c16 * 16,
                 src + (size_t)row * Cv + k0 + c16 * 8);
        }
        asm volatile("cp.async.commit_group;" ::: "memory");
    };

    load_stage(0, 0);

    const int ra = lane & 15;
    const int ca = (lane >> 4) * 8;

    for (int c = 0; c < CHUNKS; c++) {
        const int s = c & 1;
        if (c + 1 < CHUNKS) {
            load_stage(c + 1, (c + 1) & 1);
            asm volatile("cp.async.wait_group 1;" ::: "memory");
        } else {
            asm volatile("cp.async.wait_group 0;" ::: "memory");
        }
        __syncthreads();

        const uint32_t base = sb + s * STAGE_B;
        const uint32_t aH = base;
        const uint32_t bH = base + TILE_B;

#pragma unroll
        for (int ks = 0; ks < 4; ks++) {
            const int k16 = ks * 16;
            uint32_t ah[4][4], bh[2][4];
#pragma unroll
            for (int mi = 0; mi < 4; mi++) {
                uint32_t off = (warp_m * 64 + mi * 16 + ra) * RSB + (k16 + ca) * 2;
                ldx4(ah[mi], aH + off);
            }
#pragma unroll
            for (int pb = 0; pb < 2; pb++) {
                uint32_t boff = (warp_n * 32 + pb * 16 + ra) * RSB + (k16 + ca) * 2;
                ldx4(bh[pb], bH + boff);
            }
#pragma unroll
            for (int mi = 0; mi < 4; mi++)
#pragma unroll
                for (int pb = 0; pb < 2; pb++)
#pragma unroll
                    for (int hf = 0; hf < 2; hf++)
                        mma16816(acc[mi][pb * 2 + hf], ah[mi],
                                 bh[pb][hf], bh[pb][hf + 2]);
        }
        __syncthreads();
    }

    const int er = lane >> 2;
    const int ec = (lane & 3) * 2;

    if (MODE == 0) {
#pragma unroll
        for (int mi = 0; mi < 4; mi++)
#pragma unroll
            for (int ni = 0; ni < 4; ni++) {
                int m = m0 + warp_m * 64 + mi * 16 + er;
                int n = n0 + warp_n * 32 + ni * 8 + ec;
                float bb0 = b0p[n], bb1 = b0p[n + 1];
                float* d = acc[mi][ni];
                *(float2*)(Y + (size_t)m * Cv + n) = make_float2(d[0] + bb0, d[1] + bb1);
                *(float2*)(Y + (size_t)(m + 8) * Cv + n) = make_float2(d[2] + bb0, d[3] + bb1);
            }
    } else {
        const int sel = blockIdx.x >> 3;
        const int nl0 = (blockIdx.x & 7) * 128;
        const float* bias = (sel == 0) ? b0p : (sel == 1) ? b1p : b2p;
        h16* Yh = (sel == 0) ? O0h : (sel == 1) ? O1h : O2h;
        h16* Yl = (sel == 0) ? O0l : (sel == 1) ? O1l : O2l;
#pragma unroll
        for (int mi = 0; mi < 4; mi++)
#pragma unroll
            for (int ni = 0; ni < 4; ni++) {
                int m = m0 + warp_m * 64 + mi * 16 + er;
                int n = nl0 + warp_n * 32 + ni * 8 + ec;
                float bb0 = bias[n], bb1 = bias[n + 1];
                float* d = acc[mi][ni];
#pragma unroll
                for (int rr = 0; rr < 2; rr++) {
                    int mm = m + rr * 8;
                    float v0 = d[rr * 2 + 0] + bb0;
                    float v1 = d[rr * 2 + 1] + bb1;
                    h16 h0 = __float2half_rn(v0);
                    h16 h1 = __float2half_rn(v1);
                    __half2 hp(h0, h1);
                    *(uint32_t*)(Yh + (size_t)mm * Cv + n) = *(uint32_t*)&hp;
                    if (Yl)
                        *(uint32_t*)(Yl + (size_t)mm * Cv + n) =
                            pack2h(v0 - __half2float(h0), v1 - __half2float(h1));
                }
            }
    }
}

// ---------------------------------------------------------------------------
// Tensor-core block-sparse attention (unchanged, validated):
// S ~= Qh*(Kh+Kl); O ~= Ph*(Vh+Vl). One CTA per (q-block, head, batch).
// ---------------------------------------------------------------------------
#define ARS 144
#define PRS 272
#define OFF_QH   0
#define OFF_KH   9216
#define OFF_KL   27648
#define OFF_VTH  46080
#define OFF_VTL  63488
#define OFF_PH   80896
#define OFF_RMAX 98304
#define OFF_RSUM 98816
#define ATTN_SMEM 99328

__global__ __launch_bounds__(256, 1) void attn_tc(
    const h16* __restrict__ Qh,
    const h16* __restrict__ Kh, const h16* __restrict__ Kl,
    const h16* __restrict__ Vh, const h16* __restrict__ Vl,
    h16* __restrict__ Oh)
{
    extern __shared__ __align__(16) char sm[];
    const int tid  = threadIdx.x;
    const int lane = tid & 31;
    const int wid  = tid >> 5;
    const int warp_m = wid >> 1;
    const int warp_n = wid & 1;
    const int nb = blockIdx.x, h = blockIdx.y, b = blockIdx.z;
    const int qrow0 = b * Nv + nb * BSv;
    const int col0  = h * Dv;
    const int kb0 = (nb > 0) ? nb - 1 : 0;

    const uint32_t sb = smem_u32(sm);

#pragma unroll
    for (int it = 0; it < 2; it++) {
        int i = it * 256 + tid;
        int r = i >> 3, c = i & 7;
        cp16(sb + OFF_QH + r * ARS + c * 16,
             Qh + (size_t)(qrow0 + r) * Cv + col0 + c * 8);
    }
#pragma unroll
    for (int it = 0; it < 8; it++) {
        int lin = it * 256 + tid;
        int t = lin >> 10, i = lin & 1023;
        int r = i >> 3, c = i & 7;
        int krow = b * Nv + (r < 64 ? kb0 * 64 + r : nb * 64 + (r - 64));
        const h16* src = (t ? Kl : Kh) + (size_t)krow * Cv + col0 + c * 8;
        cp16(sb + (t ? OFF_KL : OFF_KH) + r * ARS + c * 16, src);
    }
    asm volatile("cp.async.commit_group;" ::: "memory");

#pragma unroll
    for (int t = 0; t < 2; t++) {
        const h16* Vsrc = t ? Vl : Vh;
        char* vt = sm + (t ? OFF_VTL : OFF_VTH);
#pragma unroll
        for (int it = 0; it < 16; it++) {
            int lin = it * 256 + tid;
            int key = lin >> 5, dp = lin & 31;
            int krow = b * Nv + (key < 64 ? kb0 * 64 + key : nb * 64 + (key - 64));
            uint32_t v = *(const uint32_t*)(Vsrc + (size_t)krow * Cv + col0 + dp * 2);
            *(uint16_t*)(vt + (2 * dp + 0) * PRS + key * 2) = (uint16_t)(v & 0xffff);
            *(uint16_t*)(vt + (2 * dp + 1) * PRS + key * 2) = (uint16_t)(v >> 16);
        }
    }
    asm volatile("cp.async.wait_group 0;" ::: "memory");
    __syncthreads();

    const int ra = lane & 15;
    const int ca = (lane >> 4) * 8;
    float acc[8][4];
#pragma unroll
    for (int ni = 0; ni < 8; ni++)
#pragma unroll
        for (int f = 0; f < 4; f++) acc[ni][f] = 0.f;

#pragma unroll
    for (int ks = 0; ks < 4; ks++) {
        uint32_t ah[4];
        uint32_t aoff = (warp_m * 16 + ra) * ARS + (ks * 16 + ca) * 2;
        ldx4(ah, sb + OFF_QH + aoff);
        uint32_t bh[4][4], bl[4][4];
#pragma unroll
        for (int pb = 0; pb < 4; pb++) {
            uint32_t boff = (warp_n * 64 + pb * 16 + ra) * ARS + (ks * 16 + ca) * 2;
            ldx4(bh[pb], sb + OFF_KH + boff);
            ldx4(bl[pb], sb + OFF_KL + boff);
        }
#pragma unroll
        for (int pb = 0; pb < 4; pb++)
#pragma unroll
            for (int hf = 0; hf < 2; hf++) {
                int ni = pb * 2 + hf;
                mma16816(acc[ni], ah, bh[pb][hf], bh[pb][hf + 2]);
                mma16816(acc[ni], ah, bl[pb][hf], bl[pb][hf + 2]);
            }
    }

    const int er = lane >> 2;
    const int ec = (lane & 3) * 2;
    const int iq = warp_m * 16 + er;
    const float scale = 0.125f;

#pragma unroll
    for (int ni = 0; ni < 8; ni++)
#pragma unroll
        for (int f = 0; f < 4; f++) {
            int i = iq + ((f >= 2) ? 8 : 0);
            int j = warp_n * 64 + ni * 8 + ec + (f & 1);
            bool valid = (64 + i >= j) && (nb > 0 || j >= 64);
            acc[ni][f] = valid ? acc[ni][f] * scale : -1e30f;
        }

    float m0 = -1e30f, m1 = -1e30f;
#pragma unroll
    for (int ni = 0; ni < 8; ni++) {
        m0 = fmaxf(m0, fmaxf(acc[ni][0], acc[ni][1]));
        m1 = fmaxf(m1, fmaxf(acc[ni][2], acc[ni][3]));
    }
    m0 = fmaxf(m0, __shfl_xor_sync(0xffffffffu, m0, 1));
    m0 = fmaxf(m0, __shfl_xor_sync(0xffffffffu, m0, 2));
    m1 = fmaxf(m1, __shfl_xor_sync(0xffffffffu, m1, 1));
    m1 = fmaxf(m1, __shfl_xor_sync(0xffffffffu, m1, 2));
    float* rmax = (float*)(sm + OFF_RMAX);
    if ((lane & 3) == 0) {
        rmax[iq * 2 + warp_n] = m0;
        rmax[(iq + 8) * 2 + warp_n] = m1;
    }
    __syncthreads();
    float g0 = fmaxf(rmax[iq * 2], rmax[iq * 2 + 1]);
    float g1 = fmaxf(rmax[(iq + 8) * 2], rmax[(iq + 8) * 2 + 1]);

    float s0 = 0.f, s1 = 0.f;
#pragma unroll
    for (int ni = 0; ni < 8; ni++) {
        acc[ni][0] = __expf(acc[ni][0] - g0);
        acc[ni][1] = __expf(acc[ni][1] - g0);
        acc[ni][2] = __expf(acc[ni][2] - g1);
        acc[ni][3] = __expf(acc[ni][3] - g1);
        s0 += acc[ni][0] + acc[ni][1];
        s1 += acc[ni][2] + acc[ni][3];
    }
    s0 += __shfl_xor_sync(0xffffffffu, s0, 1);
    s0 += __shfl_xor_sync(0xffffffffu, s0, 2);
    s1 += __shfl_xor_sync(0xffffffffu, s1, 1);
    s1 += __shfl_xor_sync(0xffffffffu, s1, 2);
    float* rsum = (float*)(sm + OFF_RSUM);
    if ((lane & 3) == 0) {
        rsum[iq * 2 + warp_n] = s0;
        rsum[(iq + 8) * 2 + warp_n] = s1;
    }
    __syncthreads();
    float inv0 = 1.f / (rsum[iq * 2] + rsum[iq * 2 + 1]);
    float inv1 = 1.f / (rsum[(iq + 8) * 2] + rsum[(iq + 8) * 2 + 1]);

#pragma unroll
    for (int ni = 0; ni < 8; ni++) {
        int j = warp_n * 64 + ni * 8 + ec;
        *(uint32_t*)(sm + OFF_PH + iq * PRS + j * 2) =
            pack2h(acc[ni][0] * inv0, acc[ni][1] * inv0);
        *(uint32_t*)(sm + OFF_PH + (iq + 8) * PRS + j * 2) =
            pack2h(acc[ni][2] * inv1, acc[ni][3] * inv1);
    }
    __syncthreads();

    float oacc[4][4];
#pragma unroll
    for (int ni = 0; ni < 4; ni++)
#pragma unroll
        for (int f = 0; f < 4; f++) oacc[ni][f] = 0.f;

#pragma unroll
    for (int ks = 0; ks < 8; ks++) {
        uint32_t ph[4];
        uint32_t aoff = (warp_m * 16 + ra) * PRS + (ks * 16 + ca) * 2;
        ldx4(ph, sb + OFF_PH + aoff);
        uint32_t vh[2][4], vl[2][4];
#pragma unroll
        for (int pb = 0; pb < 2; pb++) {
            uint32_t boff = (warp_n * 32 + pb * 16 + ra) * PRS + (ks * 16 + ca) * 2;
            ldx4(vh[pb], sb + OFF_VTH + boff);
            ldx4(vl[pb], sb + OFF_VTL + boff);
        }
#pragma unroll
        for (int pb = 0; pb < 2; pb++)
#pragma unroll
            for (int hf = 0; hf < 2; hf++) {
                int ni = pb * 2 + hf;
                mma16816(oacc[ni], ph, vh[pb][hf], vh[pb][hf + 2]);
                mma16816(oacc[ni], ph, vl[pb][hf], vl[pb][hf + 2]);
            }
    }

#pragma unroll
    for (int ni = 0; ni < 4; ni++) {
        int colg = col0 + warp_n * 32 + ni * 8 + ec;
        float* d = oacc[ni];
#pragma unroll
        for (int rr = 0; rr < 2; rr++) {
            int row = qrow0 + warp_m * 16 + er + rr * 8;
            *(uint32_t*)(Oh + (size_t)row * Cv + colg) =
                pack2h(d[rr * 2 + 0], d[rr * 2 + 1]);
        }
    }
}

// ---------------------------------------------------------------------------
extern "C" void kernel_launch(void* const* d_in, const int* in_sizes, int n_in,
                              void* d_out, int out_size)
{
    const float* x  = (const float*)d_in[0];
    const float* Wq = (const float*)d_in[1];
    const float* bq = (const float*)d_in[2];
    const float* Wk = (const float*)d_in[3];
    const float* bk = (const float*)d_in[4];
    const float* Wv = (const float*)d_in[5];
    const float* bv = (const float*)d_in[6];
    const float* Wo = (const float*)d_in[7];
    const float* bo = (const float*)d_in[8];
    float* out = (float*)d_out;

    void* p;
    h16 *Xh, *Qh, *Kh, *Kl, *Vh, *Vl, *Oh, *Wh;
    cudaGetSymbolAddress(&p, g_Xh); Xh = (h16*)p;
    cudaGetSymbolAddress(&p, g_Qh); Qh = (h16*)p;
    cudaGetSymbolAddress(&p, g_Kh); Kh = (h16*)p;
    cudaGetSymbolAddress(&p, g_Kl); Kl = (h16*)p;
    cudaGetSymbolAddress(&p, g_Vh); Vh = (h16*)p;
    cudaGetSymbolAddress(&p, g_Vl); Vl = (h16*)p;
    cudaGetSymbolAddress(&p, g_Oh); Oh = (h16*)p;
    cudaGetSymbolAddress(&p, g_Wh); Wh = (h16*)p;

    cudaFuncSetAttribute(gemm_mma<0>, cudaFuncAttributeMaxDynamicSharedMemorySize, GEMM_SMEM);
    cudaFuncSetAttribute(gemm_mma<1>, cudaFuncAttributeMaxDynamicSharedMemorySize, GEMM_SMEM);
    cudaFuncSetAttribute(attn_tc, cudaFuncAttributeMaxDynamicSharedMemorySize, ATTN_SMEM);

    const size_t WSZ = (size_t)Cv * Cv;
    const int xn4 = Mv * Cv / 4;
    const int wn4 = (int)(WSZ / 4);

    split_hi<<<xn4 / 256, 256>>>(x, Xh, xn4);
    split_hi<<<wn4 / 256, 256>>>(Wq, Wh + 0 * WSZ, wn4);
    split_hi<<<wn4 / 256, 256>>>(Wk, Wh + 1 * WSZ, wn4);
    split_hi<<<wn4 / 256, 256>>>(Wv, Wh + 2 * WSZ, wn4);
    split_hi<<<wn4 / 256, 256>>>(Wo, Wh + 3 * WSZ, wn4);

    // merged QKV projection (single-product fp16); K,V also emit lo residuals
    dim3 gq(24, Mv / 128);   // (24, 128)
    gemm_mma<1><<<gq, 256, GEMM_SMEM>>>(Xh, Wh, bq, bk, bv,
                                        nullptr, Qh, nullptr, Kh, Kl, Vh, Vl);

    // tensor-core attention -> Oh (fp16)
    dim3 ga(NBv, Hv, Bv);
    attn_tc<<<ga, 256, ATTN_SMEM>>>(Qh, Kh, Kl, Vh, Vl, Oh);

    // output projection (single-product fp16, fp32 out)
    dim3 gg(Cv / 128, Mv / 128);   // (8, 128)
    gemm_mma<0><<<gg, 256, GEMM_SMEM>>>(Oh, Wh + 3 * WSZ,
                                        bo, nullptr, nullptr, out,
                                        nullptr, nullptr, nullptr, nullptr,
                                        nullptr, nullptr);
}

// round 15
// speedup vs baseline: 1.9641x; 1.1293x over previous
#include <cuda_runtime.h>
#include <cuda_fp16.h>
#include <cstdint>
#include <math.h>

// Problem constants
#define Bv   4
#define Nv   4096
#define Cv   1024
#define Hv   16
#define Dv   64
#define BSv  64
#define NBv  64
#define Mv   (Bv * Nv)   // 16384 rows

typedef __half h16;

// ---------------------------------------------------------------------------
// Scratch (device globals; no runtime allocation allowed)
// ---------------------------------------------------------------------------
__device__ h16 g_Xh[(size_t)Mv * Cv];
__device__ h16 g_Qh[(size_t)Mv * Cv];
__device__ h16 g_Kh[(size_t)Mv * Cv];
__device__ h16 g_Vh[(size_t)Mv * Cv];
__device__ h16 g_Oh[(size_t)Mv * Cv];
__device__ h16 g_Wh[4 * (size_t)Cv * Cv];

__device__ __forceinline__ uint32_t smem_u32(const void* p) {
    return (uint32_t)__cvta_generic_to_shared(p);
}

__device__ __forceinline__ void cp16(uint32_t saddr, const void* gaddr) {
    asm volatile("cp.async.cg.shared.global [%0], [%1], 16;"
                 :: "r"(saddr), "l"(gaddr));
}

__device__ __forceinline__ void ldx4(uint32_t* r, uint32_t addr) {
    asm volatile("ldmatrix.sync.aligned.m8n8.x4.shared.b16 {%0,%1,%2,%3}, [%4];"
                 : "=r"(r[0]), "=r"(r[1]), "=r"(r[2]), "=r"(r[3]) : "r"(addr));
}

__device__ __forceinline__ void mma16816(float* d, const uint32_t* a,
                                         uint32_t b0, uint32_t b1) {
    asm volatile("mma.sync.aligned.m16n8k16.row.col.f32.f16.f16.f32 "
                 "{%0,%1,%2,%3}, {%4,%5,%6,%7}, {%8,%9}, {%0,%1,%2,%3};"
                 : "+f"(d[0]), "+f"(d[1]), "+f"(d[2]), "+f"(d[3])
                 : "r"(a[0]), "r"(a[1]), "r"(a[2]), "r"(a[3]), "r"(b0), "r"(b1));
}

__device__ __forceinline__ uint32_t pack2h(float a, float b) {
    __half2 t(__float2half_rn(a), __float2half_rn(b));
    return *(uint32_t*)&t;
}

// ---------------------------------------------------------------------------
// Split: fp32 -> fp16 (round-to-nearest)
// ---------------------------------------------------------------------------
__global__ __launch_bounds__(256) void split_hi(
    const float* __restrict__ src, h16* __restrict__ hi, int n4)
{
    int i = blockIdx.x * blockDim.x + threadIdx.x;
    if (i >= n4) return;
    float4 v = *(const float4*)(src + (size_t)i * 4);
    uint2 hp;
    hp.x = pack2h(v.x, v.y); hp.y = pack2h(v.z, v.w);
    *(uint2*)(hi + (size_t)i * 4) = hp;
}

// ---------------------------------------------------------------------------
// HMMA GEMM, single-product fp16 (fp32 accum). CTA 128x128, 8 warps 64x32.
// 2-stage cp.async ring (73.7 KB -> >=2 CTAs/SM).
// MODE 0: fp32 out (+bias b0p).
// MODE 1: merged QKV — grid.x=24; sel=blockIdx.x>>3 -> (Qh, Kh, Vh) fp16 out.
// ---------------------------------------------------------------------------
#define CHUNKS   16
#define RSB      144
#define TILE_B   (128 * RSB)               // 18432
#define STAGE_B  (2 * TILE_B)              // 36864
#define GEMM_SMEM (2 * STAGE_B)            // 73728

template<int MODE>
__global__ __launch_bounds__(256, 2) void gemm_mma(
    const h16* __restrict__ Ah, const h16* __restrict__ Bh,
    const float* __restrict__ b0p, const float* __restrict__ b1p,
    const float* __restrict__ b2p,
    float* __restrict__ Y,
    h16* __restrict__ O0h, h16* __restrict__ O1h, h16* __restrict__ O2h)
{
    extern __shared__ __align__(16) char smem[];

    const int tid   = threadIdx.x;
    const int lane  = tid & 31;
    const int wid   = tid >> 5;
    const int warp_m = wid >> 2;     // 0..1 : 64 rows
    const int warp_n = wid & 3;      // 0..3 : 32 cols
    const int n0 = blockIdx.x * 128;       // col into (possibly concat) B
    const int m0 = blockIdx.y * 128;

    const h16* srcA = Ah + (size_t)m0 * Cv;
    const h16* srcB = Bh + (size_t)n0 * Cv;

    const uint32_t sb = smem_u32(smem);

    float acc[4][4][4];
#pragma unroll
    for (int mi = 0; mi < 4; mi++)
#pragma unroll
        for (int ni = 0; ni < 4; ni++)
#pragma unroll
            for (int f = 0; f < 4; f++) acc[mi][ni][f] = 0.f;

    auto load_stage = [&](int c, int s) {
        const int k0 = c * 64;
        const uint32_t base = sb + s * STAGE_B;
#pragma unroll
        for (int j = 0; j < 8; j++) {
            int chunk = tid + j * 256;       // 0..2047
            int t   = chunk >> 10;           // 0=A, 1=B
            int i   = chunk & 1023;
            int row = i >> 3;
            int c16 = i & 7;
            const h16* src = t ? srcB : srcA;
            cp16(base + t * TILE_B + row * RSB + c16 * 16,
                 src + (size_t)row * Cv + k0 + c16 * 8);
        }
        asm volatile("cp.async.commit_group;" ::: "memory");
    };

    load_stage(0, 0);

    const int ra = lane & 15;
    const int ca = (lane >> 4) * 8;

    for (int c = 0; c < CHUNKS; c++) {
        const int s = c & 1;
        if (c + 1 < CHUNKS) {
            load_stage(c + 1, (c + 1) & 1);
            asm volatile("cp.async.wait_group 1;" ::: "memory");
        } else {
            asm volatile("cp.async.wait_group 0;" ::: "memory");
        }
        __syncthreads();

        const uint32_t base = sb + s * STAGE_B;
        const uint32_t aH = base;
        const uint32_t bH = base + TILE_B;

#pragma unroll
        for (int ks = 0; ks < 4; ks++) {
            const int k16 = ks * 16;
            uint32_t ah[4][4], bh[2][4];
#pragma unroll
            for (int mi = 0; mi < 4; mi++) {
                uint32_t off = (warp_m * 64 + mi * 16 + ra) * RSB + (k16 + ca) * 2;
                ldx4(ah[mi], aH + off);
            }
#pragma unroll
            for (int pb = 0; pb < 2; pb++) {
                uint32_t boff = (warp_n * 32 + pb * 16 + ra) * RSB + (k16 + ca) * 2;
                ldx4(bh[pb], bH + boff);
            }
#pragma unroll
            for (int mi = 0; mi < 4; mi++)
#pragma unroll
                for (int pb = 0; pb < 2; pb++)
#pragma unroll
                    for (int hf = 0; hf < 2; hf++)
                        mma16816(acc[mi][pb * 2 + hf], ah[mi],
                                 bh[pb][hf], bh[pb][hf + 2]);
        }
        __syncthreads();
    }

    const int er = lane >> 2;
    const int ec = (lane & 3) * 2;

    if (MODE == 0) {
#pragma unroll
        for (int mi = 0; mi < 4; mi++)
#pragma unroll
            for (int ni = 0; ni < 4; ni++) {
                int m = m0 + warp_m * 64 + mi * 16 + er;
                int n = n0 + warp_n * 32 + ni * 8 + ec;
                float bb0 = b0p[n], bb1 = b0p[n + 1];
                float* d = acc[mi][ni];
                *(float2*)(Y + (size_t)m * Cv + n) = make_float2(d[0] + bb0, d[1] + bb1);
                *(float2*)(Y + (size_t)(m + 8) * Cv + n) = make_float2(d[2] + bb0, d[3] + bb1);
            }
    } else {
        const int sel = blockIdx.x >> 3;
        const int nl0 = (blockIdx.x & 7) * 128;
        const float* bias = (sel == 0) ? b0p : (sel == 1) ? b1p : b2p;
        h16* Yh = (sel == 0) ? O0h : (sel == 1) ? O1h : O2h;
#pragma unroll
        for (int mi = 0; mi < 4; mi++)
#pragma unroll
            for (int ni = 0; ni < 4; ni++) {
                int m = m0 + warp_m * 64 + mi * 16 + er;
                int n = nl0 + warp_n * 32 + ni * 8 + ec;
                float bb0 = bias[n], bb1 = bias[n + 1];
                float* d = acc[mi][ni];
#pragma unroll
                for (int rr = 0; rr < 2; rr++) {
                    int mm = m + rr * 8;
                    *(uint32_t*)(Yh + (size_t)mm * Cv + n) =
                        pack2h(d[rr * 2 + 0] + bb0, d[rr * 2 + 1] + bb1);
                }
            }
    }
}

// ---------------------------------------------------------------------------
// Tensor-core block-sparse attention, plain fp16 (Q,K,V single precision).
// One CTA per (q-block, head, batch). Window = [prev (clamped), self].
// smem 63.5 KB -> up to 3 CTAs/SM.
// ---------------------------------------------------------------------------
#define ARS 144
#define PRS 272
#define OFF_QH   0
#define OFF_KH   9216
#define OFF_VT   27648
#define OFF_PH   45056
#define OFF_RMAX 62464
#define OFF_RSUM 62976
#define ATTN_SMEM 63488

__global__ __launch_bounds__(256, 2) void attn_tc(
    const h16* __restrict__ Qh, const h16* __restrict__ Kh,
    const h16* __restrict__ Vh, h16* __restrict__ Oh)
{
    extern __shared__ __align__(16) char sm[];
    const int tid  = threadIdx.x;
    const int lane = tid & 31;
    const int wid  = tid >> 5;
    const int warp_m = wid >> 1;          // 0..3 : 16 q-rows
    const int warp_n = wid & 1;           // 0..1
    const int nb = blockIdx.x, h = blockIdx.y, b = blockIdx.z;
    const int qrow0 = b * Nv + nb * BSv;
    const int col0  = h * Dv;
    const int kb0 = (nb > 0) ? nb - 1 : 0;   // clamped (masked when nb==0)

    const uint32_t sb = smem_u32(sm);

    // ---- loads: Q, K via cp.async; V transposed via scalar stores ----
#pragma unroll
    for (int it = 0; it < 2; it++) {
        int i = it * 256 + tid;              // 0..511
        int r = i >> 3, c = i & 7;
        cp16(sb + OFF_QH + r * ARS + c * 16,
             Qh + (size_t)(qrow0 + r) * Cv + col0 + c * 8);
    }
#pragma unroll
    for (int it = 0; it < 4; it++) {
        int i = it * 256 + tid;              // 0..1023
        int r = i >> 3, c = i & 7;
        int krow = b * Nv + (r < 64 ? kb0 * 64 + r : nb * 64 + (r - 64));
        cp16(sb + OFF_KH + r * ARS + c * 16,
             Kh + (size_t)krow * Cv + col0 + c * 8);
    }
    asm volatile("cp.async.commit_group;" ::: "memory");

    {
        char* vt = sm + OFF_VT;
#pragma unroll
        for (int it = 0; it < 16; it++) {
            int lin = it * 256 + tid;        // 0..4095
            int key = lin >> 5, dp = lin & 31;
            int krow = b * Nv + (key < 64 ? kb0 * 64 + key : nb * 64 + (key - 64));
            uint32_t v = *(const uint32_t*)(Vh + (size_t)krow * Cv + col0 + dp * 2);
            *(uint16_t*)(vt + (2 * dp + 0) * PRS + key * 2) = (uint16_t)(v & 0xffff);
            *(uint16_t*)(vt + (2 * dp + 1) * PRS + key * 2) = (uint16_t)(v >> 16);
        }
    }
    asm volatile("cp.async.wait_group 0;" ::: "memory");
    __syncthreads();

    // ---- QK^T : per warp 16 q-rows x 64 key-cols ----
    const int ra = lane & 15;
    const int ca = (lane >> 4) * 8;
    float acc[8][4];
#pragma unroll
    for (int ni = 0; ni < 8; ni++)
#pragma unroll
        for (int f = 0; f < 4; f++) acc[ni][f] = 0.f;

#pragma unroll
    for (int ks = 0; ks < 4; ks++) {
        uint32_t ah[4];
        uint32_t aoff = (warp_m * 16 + ra) * ARS + (ks * 16 + ca) * 2;
        ldx4(ah, sb + OFF_QH + aoff);
        uint32_t bh[4][4];
#pragma unroll
        for (int pb = 0; pb < 4; pb++) {
            uint32_t boff = (warp_n * 64 + pb * 16 + ra) * ARS + (ks * 16 + ca) * 2;
            ldx4(bh[pb], sb + OFF_KH + boff);
        }
#pragma unroll
        for (int pb = 0; pb < 4; pb++)
#pragma unroll
            for (int hf = 0; hf < 2; hf++)
                mma16816(acc[pb * 2 + hf], ah, bh[pb][hf], bh[pb][hf + 2]);
    }

    // ---- mask + softmax ----
    const int er = lane >> 2;
    const int ec = (lane & 3) * 2;
    const int iq = warp_m * 16 + er;
    const float scale = 0.125f;

#pragma unroll
    for (int ni = 0; ni < 8; ni++)
#pragma unroll
        for (int f = 0; f < 4; f++) {
            int i = iq + ((f >= 2) ? 8 : 0);
            int j = warp_n * 64 + ni * 8 + ec + (f & 1);
            bool valid = (64 + i >= j) && (nb > 0 || j >= 64);
            acc[ni][f] = valid ? acc[ni][f] * scale : -1e30f;
        }

    float m0 = -1e30f, m1 = -1e30f;
#pragma unroll
    for (int ni = 0; ni < 8; ni++) {
        m0 = fmaxf(m0, fmaxf(acc[ni][0], acc[ni][1]));
        m1 = fmaxf(m1, fmaxf(acc[ni][2], acc[ni][3]));
    }
    m0 = fmaxf(m0, __shfl_xor_sync(0xffffffffu, m0, 1));
    m0 = fmaxf(m0, __shfl_xor_sync(0xffffffffu, m0, 2));
    m1 = fmaxf(m1, __shfl_xor_sync(0xffffffffu, m1, 1));
    m1 = fmaxf(m1, __shfl_xor_sync(0xffffffffu, m1, 2));
    float* rmax = (float*)(sm + OFF_RMAX);
    if ((lane & 3) == 0) {
        rmax[iq * 2 + warp_n] = m0;
        rmax[(iq + 8) * 2 + warp_n] = m1;
    }
    __syncthreads();
    float g0 = fmaxf(rmax[iq * 2], rmax[iq * 2 + 1]);
    float g1 = fmaxf(rmax[(iq + 8) * 2], rmax[(iq + 8) * 2 + 1]);

    float s0 = 0.f, s1 = 0.f;
#pragma unroll
    for (int ni = 0; ni < 8; ni++) {
        acc[ni][0] = __expf(acc[ni][0] - g0);
        acc[ni][1] = __expf(acc[ni][1] - g0);
        acc[ni][2] = __expf(acc[ni][2] - g1);
        acc[ni][3] = __expf(acc[ni][3] - g1);
        s0 += acc[ni][0] + acc[ni][1];
        s1 += acc[ni][2] + acc[ni][3];
    }
    s0 += __shfl_xor_sync(0xffffffffu, s0, 1);
    s0 += __shfl_xor_sync(0xffffffffu, s0, 2);
    s1 += __shfl_xor_sync(0xffffffffu, s1, 1);
    s1 += __shfl_xor_sync(0xffffffffu, s1, 2);
    float* rsum = (float*)(sm + OFF_RSUM);
    if ((lane & 3) == 0) {
        rsum[iq * 2 + warp_n] = s0;
        rsum[(iq + 8) * 2 + warp_n] = s1;
    }
    __syncthreads();
    float inv0 = 1.f / (rsum[iq * 2] + rsum[iq * 2 + 1]);
    float inv1 = 1.f / (rsum[(iq + 8) * 2] + rsum[(iq + 8) * 2 + 1]);

    // write P (fp16) to smem
#pragma unroll
    for (int ni = 0; ni < 8; ni++) {
        int j = warp_n * 64 + ni * 8 + ec;
        *(uint32_t*)(sm + OFF_PH + iq * PRS + j * 2) =
            pack2h(acc[ni][0] * inv0, acc[ni][1] * inv0);
        *(uint32_t*)(sm + OFF_PH + (iq + 8) * PRS + j * 2) =
            pack2h(acc[ni][2] * inv1, acc[ni][3] * inv1);
    }
    __syncthreads();

    // ---- P @ V : per warp 16 q-rows x 32 d-cols ----
    float oacc[4][4];
#pragma unroll
    for (int ni = 0; ni < 4; ni++)
#pragma unroll
        for (int f = 0; f < 4; f++) oacc[ni][f] = 0.f;

#pragma unroll
    for (int ks = 0; ks < 8; ks++) {
        uint32_t ph[4];
        uint32_t aoff = (warp_m * 16 + ra) * PRS + (ks * 16 + ca) * 2;
        ldx4(ph, sb + OFF_PH + aoff);
        uint32_t vh[2][4];
#pragma unroll
        for (int pb = 0; pb < 2; pb++) {
            uint32_t boff = (warp_n * 32 + pb * 16 + ra) * PRS + (ks * 16 + ca) * 2;
            ldx4(vh[pb], sb + OFF_VT + boff);
        }
#pragma unroll
        for (int pb = 0; pb < 2; pb++)
#pragma unroll
            for (int hf = 0; hf < 2; hf++)
                mma16816(oacc[pb * 2 + hf], ph, vh[pb][hf], vh[pb][hf + 2]);
    }

    // ---- epilogue: O -> global fp16 ----
#pragma unroll
    for (int ni = 0; ni < 4; ni++) {
        int colg = col0 + warp_n * 32 + ni * 8 + ec;
        float* d = oacc[ni];
#pragma unroll
        for (int rr = 0; rr < 2; rr++) {
            int row = qrow0 + warp_m * 16 + er + rr * 8;
            *(uint32_t*)(Oh + (size_t)row * Cv + colg) =
                pack2h(d[rr * 2 + 0], d[rr * 2 + 1]);
        }
    }
}

// ---------------------------------------------------------------------------
extern "C" void kernel_launch(void* const* d_in, const int* in_sizes, int n_in,
                              void* d_out, int out_size)
{
    const float* x  = (const float*)d_in[0];
    const float* Wq = (const float*)d_in[1];
    const float* bq = (const float*)d_in[2];
    const float* Wk = (const float*)d_in[3];
    const float* bk = (const float*)d_in[4];
    const float* Wv = (const float*)d_in[5];
    const float* bv = (const float*)d_in[6];
    const float* Wo = (const float*)d_in[7];
    const float* bo = (const float*)d_in[8];
    float* out = (float*)d_out;

    void* p;
    h16 *Xh, *Qh, *Kh, *Vh, *Oh, *Wh;
    cudaGetSymbolAddress(&p, g_Xh); Xh = (h16*)p;
    cudaGetSymbolAddress(&p, g_Qh); Qh = (h16*)p;
    cudaGetSymbolAddress(&p, g_Kh); Kh = (h16*)p;
    cudaGetSymbolAddress(&p, g_Vh); Vh = (h16*)p;
    cudaGetSymbolAddress(&p, g_Oh); Oh = (h16*)p;
    cudaGetSymbolAddress(&p, g_Wh); Wh = (h16*)p;

    cudaFuncSetAttribute(gemm_mma<0>, cudaFuncAttributeMaxDynamicSharedMemorySize, GEMM_SMEM);
    cudaFuncSetAttribute(gemm_mma<1>, cudaFuncAttributeMaxDynamicSharedMemorySize, GEMM_SMEM);
    cudaFuncSetAttribute(attn_tc, cudaFuncAttributeMaxDynamicSharedMemorySize, ATTN_SMEM);

    const size_t WSZ = (size_t)Cv * Cv;
    const int xn4 = Mv * Cv / 4;
    const int wn4 = (int)(WSZ / 4);

    split_hi<<<xn4 / 256, 256>>>(x, Xh, xn4);
    split_hi<<<wn4 / 256, 256>>>(Wq, Wh + 0 * WSZ, wn4);
    split_hi<<<wn4 / 256, 256>>>(Wk, Wh + 1 * WSZ, wn4);
    split_hi<<<wn4 / 256, 256>>>(Wv, Wh + 2 * WSZ, wn4);
    split_hi<<<wn4 / 256, 256>>>(Wo, Wh + 3 * WSZ, wn4);

    // merged QKV projection (single-product fp16, fp16 outputs)
    dim3 gq(24, Mv / 128);   // (24, 128)
    gemm_mma<1><<<gq, 256, GEMM_SMEM>>>(Xh, Wh, bq, bk, bv,
                                        nullptr, Qh, Kh, Vh);

    // tensor-core attention -> Oh (fp16)
    dim3 ga(NBv, Hv, Bv);
    attn_tc<<<ga, 256, ATTN_SMEM>>>(Qh, Kh, Vh, Oh);

    // output projection (single-product fp16, fp32 out)
    dim3 gg(Cv / 128, Mv / 128);   // (8, 128)
    gemm_mma<0><<<gg, 256, GEMM_SMEM>>>(Oh, Wh + 3 * WSZ,
                                        bo, nullptr, nullptr, out,
                                        nullptr, nullptr, nullptr);
}